// round 3
// baseline (speedup 1.0000x reference)
#include <cuda_runtime.h>
#include <cstdint>

#define NNODES 50000
#define NEDGES 800000
#define NLBL   100000
#define FIN    128
#define FHID   128
#define FOUT   64

// ---------------- device scratch (static, no runtime allocation) ----------------
__device__ int   g_cnt[NNODES];
__device__ int   g_fill[NNODES];
__device__ int   g_rowstart[NNODES + 1];
__device__ float g_dinv[NNODES];
__device__ int   g_srcs[NEDGES];
__device__ __align__(16) float g_hh[(size_t)NNODES * 128];    // GEMM out, pre-scaled by dinv[row]
__device__ __align__(16) float g_z[(size_t)NNODES * 128];     // layer activation
__device__ __align__(16) float g_zout[(size_t)NNODES * 64];   // final embeddings

// ---------------- CSR build ----------------
__global__ void k_zero(int n) {
    int i = blockIdx.x * blockDim.x + threadIdx.x;
    if (i < n) { g_cnt[i] = 0; g_fill[i] = 0; }
}

__global__ void k_count(const int* __restrict__ ei, int E) {
    int e = blockIdx.x * blockDim.x + threadIdx.x;
    if (e >= E) return;
    int d = ei[(size_t)E + e];
    atomicAdd(&g_cnt[d], 1);
}

// single-block exclusive scan over NNODES + dinv computation
__global__ void k_scan(int n) {
    const int T = 1024;
    const int CH = (NNODES + T - 1) / T;   // 49
    __shared__ int sums[T];
    int tid = threadIdx.x;
    int b = tid * CH;
    int e = min(b + CH, n);
    int s = 0;
    for (int i = b; i < e; i++) s += g_cnt[i];
    sums[tid] = s;
    __syncthreads();
    // inclusive Hillis-Steele
    for (int off = 1; off < T; off <<= 1) {
        int t = 0;
        if (tid >= off) t = sums[tid - off];
        __syncthreads();
        sums[tid] += t;
        __syncthreads();
    }
    int run = sums[tid] - s;   // exclusive prefix
    for (int i = b; i < e; i++) {
        g_rowstart[i] = run;
        int c = g_cnt[i];
        run += c;
        g_dinv[i] = rsqrtf((float)c + 1.0f);
    }
    if (tid == T - 1) g_rowstart[n] = sums[T - 1];
}

__global__ void k_fill(const int* __restrict__ ei, int E) {
    int e = blockIdx.x * blockDim.x + threadIdx.x;
    if (e >= E) return;
    int s = ei[e];
    int d = ei[(size_t)E + e];
    int pos = g_rowstart[d] + atomicAdd(&g_fill[d], 1);
    g_srcs[pos] = s;
}

// ---------------- GEMM: g_hh[row] = (A[row] @ W) * dinv[row] ----------------
// A = x (useZ=0) or g_z (useZ=1). BM=64, BN=64, BK=16, 256 threads, 4x4 micro-tile.
__global__ void __launch_bounds__(256)
k_gemm(const float* __restrict__ Ain, const float* __restrict__ W,
       int N, int Fout, int useZ) {
    const int K = 128;
    const float* A = useZ ? (const float*)g_z : Ain;
    __shared__ float xs[16][64];   // [k][row]
    __shared__ float ws[16][64];   // [k][col]
    int tid = threadIdx.x;
    int tr = tid >> 4;          // 0..15
    int tc = tid & 15;          // 0..15
    int rb = blockIdx.x * 64;
    int cb = blockIdx.y * 64;

    int lr = tid >> 2;          // A row within tile (0..63)
    int lc = (tid & 3) * 4;     // A k within tile
    int wr = tid >> 4;          // W k within tile (0..15)
    int wc = (tid & 15) * 4;    // W col within tile

    float acc[4][4] = {};

    for (int k0 = 0; k0 < K; k0 += 16) {
        int grow = rb + lr;
        float4 av = make_float4(0.f, 0.f, 0.f, 0.f);
        if (grow < N) av = *(const float4*)(A + (size_t)grow * K + k0 + lc);
        xs[lc + 0][lr] = av.x;
        xs[lc + 1][lr] = av.y;
        xs[lc + 2][lr] = av.z;
        xs[lc + 3][lr] = av.w;
        float4 wv = *(const float4*)(W + (size_t)(k0 + wr) * Fout + cb + wc);
        *(float4*)&ws[wr][wc] = wv;
        __syncthreads();
#pragma unroll
        for (int kk = 0; kk < 16; kk++) {
            float a[4], bb[4];
            *(float4*)a  = *(const float4*)&xs[kk][tr * 4];
            *(float4*)bb = *(const float4*)&ws[kk][tc * 4];
#pragma unroll
            for (int i = 0; i < 4; i++)
#pragma unroll
                for (int j = 0; j < 4; j++)
                    acc[i][j] = fmaf(a[i], bb[j], acc[i][j]);
        }
        __syncthreads();
    }
#pragma unroll
    for (int i = 0; i < 4; i++) {
        int row = rb + tr * 4 + i;
        if (row < N) {
            float dv = g_dinv[row];
            float4 o = make_float4(acc[i][0] * dv, acc[i][1] * dv,
                                   acc[i][2] * dv, acc[i][3] * dv);
            *(float4*)(g_hh + (size_t)row * Fout + cb + tc * 4) = o;
        }
    }
}

// ---------------- Aggregation: out[v] = relu?( dinv[v]*(hh[v] + sum hh[src]) + b ) ----------------
// Reads g_hh; writes g_z (toZ=1) or g_zout (toZ=0).
template <int VEC>   // VEC=4 -> F=128, VEC=2 -> F=64
__global__ void k_agg(const float* __restrict__ bias, int N, int F, int relu, int toZ) {
    int warp = (blockIdx.x * blockDim.x + threadIdx.x) >> 5;
    int lane = threadIdx.x & 31;
    if (warp >= N) return;
    int v = warp;
    int fo = lane * VEC;
    const float* hh = g_hh;

    float acc[VEC];
    {
        const float* hv = hh + (size_t)v * F + fo;
        if (VEC == 4) {
            float4 t = *(const float4*)hv;
            acc[0] = t.x; acc[1] = t.y; acc[2] = t.z; acc[3] = t.w;
        } else {
            float2 t = *(const float2*)hv;
            acc[0] = t.x; acc[1] = t.y;
        }
    }
    int s0 = g_rowstart[v], s1 = g_rowstart[v + 1];
    for (int base = s0; base < s1; base += 32) {
        int cnt = min(32, s1 - base);
        int sl = (base + lane < s1) ? g_srcs[base + lane] : 0;
#pragma unroll 4
        for (int j = 0; j < cnt; j++) {
            int s = __shfl_sync(0xffffffff, sl, j);
            const float* hs = hh + (size_t)s * F + fo;
            if (VEC == 4) {
                float4 t = *(const float4*)hs;
                acc[0] += t.x; acc[1] += t.y; acc[2] += t.z; acc[3] += t.w;
            } else {
                float2 t = *(const float2*)hs;
                acc[0] += t.x; acc[1] += t.y;
            }
        }
    }
    float dv = g_dinv[v];
    float o[VEC];
#pragma unroll
    for (int i = 0; i < VEC; i++) {
        float val = acc[i] * dv + bias[fo + i];
        if (relu) val = fmaxf(val, 0.f);
        o[i] = val;
    }
    float* op = (toZ ? g_z : g_zout) + (size_t)v * F + fo;
    if (VEC == 4) *(float4*)op = make_float4(o[0], o[1], o[2], o[3]);
    else          *(float2*)op = make_float2(o[0], o[1]);
}

// ---------------- Decode: out[j] = dot(zout[a], zout[b]) over 64 dims ----------------
__global__ void k_decode(const int* __restrict__ eli, float* __restrict__ out, int L) {
    int warp = (blockIdx.x * blockDim.x + threadIdx.x) >> 5;
    int lane = threadIdx.x & 31;
    if (warp >= L) return;
    int a = eli[warp];
    int b = eli[(size_t)L + warp];
    float2 za = *(const float2*)(g_zout + (size_t)a * 64 + lane * 2);
    float2 zb = *(const float2*)(g_zout + (size_t)b * 64 + lane * 2);
    float p = za.x * zb.x + za.y * zb.y;
#pragma unroll
    for (int off = 16; off > 0; off >>= 1)
        p += __shfl_xor_sync(0xffffffff, p, off);
    if (lane == 0) out[warp] = p;
}

// ---------------- launch ----------------
extern "C" void kernel_launch(void* const* d_in, const int* in_sizes, int n_in,
                              void* d_out, int out_size) {
    const float* x   = (const float*)d_in[0];
    const int*   ei  = (const int*)d_in[1];    // int32: JAX x64 disabled downcasts int64->int32
    const int*   eli = (const int*)d_in[2];
    const float* W1  = (const float*)d_in[3];
    const float* b1  = (const float*)d_in[4];
    const float* W2  = (const float*)d_in[5];
    const float* b2  = (const float*)d_in[6];
    const float* W3  = (const float*)d_in[7];
    const float* b3  = (const float*)d_in[8];
    float* out = (float*)d_out;

    // CSR build
    k_zero<<<(NNODES + 255) / 256, 256>>>(NNODES);
    k_count<<<(NEDGES + 255) / 256, 256>>>(ei, NEDGES);
    k_scan<<<1, 1024>>>(NNODES);
    k_fill<<<(NEDGES + 255) / 256, 256>>>(ei, NEDGES);

    dim3 gB(256);
    // layer 1: x @ W1 -> hh ; agg -> z (relu)
    {
        dim3 g((NNODES + 63) / 64, FHID / 64);
        k_gemm<<<g, gB>>>(x, W1, NNODES, FHID, 0);
        k_agg<4><<<(NNODES * 32 + 255) / 256, 256>>>(b1, NNODES, 128, 1, 1);
    }
    // layer 2: z @ W2 -> hh ; agg -> z (relu)
    {
        dim3 g((NNODES + 63) / 64, FHID / 64);
        k_gemm<<<g, gB>>>(nullptr, W2, NNODES, FHID, 1);
        k_agg<4><<<(NNODES * 32 + 255) / 256, 256>>>(b2, NNODES, 128, 1, 1);
    }
    // layer 3: z @ W3 -> hh(64-wide) ; agg -> zout (no relu)
    {
        dim3 g((NNODES + 63) / 64, FOUT / 64);
        k_gemm<<<g, gB>>>(nullptr, W3, NNODES, FOUT, 1);
        k_agg<2><<<(NNODES * 32 + 255) / 256, 256>>>(b3, NNODES, 64, 0, 0);
    }
    // decode
    k_decode<<<(NLBL * 32 + 255) / 256, 256>>>(eli, out, NLBL);
}

// round 4
// speedup vs baseline: 1.8875x; 1.8875x over previous
#include <cuda_runtime.h>
#include <cstdint>

#define NNODES 50000
#define NEDGES 800000
#define NLBL   100000
#define FIN    128
#define FHID   128
#define FOUT   64

// ---------------- device scratch (static, no runtime allocation) ----------------
__device__ int   g_cnt[NNODES];
__device__ int   g_fill[NNODES];
__device__ int   g_rowstart[NNODES + 1];
__device__ float g_dinv[NNODES];
__device__ int   g_srcs[NEDGES];
__device__ __align__(16) float g_hh[(size_t)NNODES * 128];    // GEMM out, pre-scaled by dinv[row]
__device__ __align__(16) float g_z[(size_t)NNODES * 128];     // layer activation
__device__ __align__(16) float g_zout[(size_t)NNODES * 64];   // final embeddings

// ---------------- CSR build ----------------
__global__ void k_zero(int n) {
    int i = blockIdx.x * blockDim.x + threadIdx.x;
    if (i < n) { g_cnt[i] = 0; g_fill[i] = 0; }
}

__global__ void k_count(const int* __restrict__ ei, int E) {
    int e = blockIdx.x * blockDim.x + threadIdx.x;
    if (e >= E) return;
    int d = ei[(size_t)E + e];
    atomicAdd(&g_cnt[d], 1);
}

// single-block exclusive scan over NNODES + dinv computation
__global__ void k_scan(int n) {
    const int T = 1024;
    const int CH = (NNODES + T - 1) / T;   // 49
    __shared__ int sums[T];
    int tid = threadIdx.x;
    int b = tid * CH;
    int e = min(b + CH, n);
    int s = 0;
    for (int i = b; i < e; i++) s += g_cnt[i];
    sums[tid] = s;
    __syncthreads();
    for (int off = 1; off < T; off <<= 1) {
        int t = 0;
        if (tid >= off) t = sums[tid - off];
        __syncthreads();
        sums[tid] += t;
        __syncthreads();
    }
    int run = sums[tid] - s;   // exclusive prefix
    for (int i = b; i < e; i++) {
        g_rowstart[i] = run;
        int c = g_cnt[i];
        run += c;
        g_dinv[i] = rsqrtf((float)c + 1.0f);
    }
    if (tid == T - 1) g_rowstart[n] = sums[T - 1];
}

__global__ void k_fill(const int* __restrict__ ei, int E) {
    int e = blockIdx.x * blockDim.x + threadIdx.x;
    if (e >= E) return;
    int s = ei[e];
    int d = ei[(size_t)E + e];
    int pos = g_rowstart[d] + atomicAdd(&g_fill[d], 1);
    g_srcs[pos] = s;
}

// ---------------- helpers for tf32 tensor-core GEMM ----------------
__device__ __forceinline__ uint32_t f2tf32(float f) {
    uint32_t r;
    asm("cvt.rna.tf32.f32 %0, %1;" : "=r"(r) : "f"(f));
    return r;
}

__device__ __forceinline__ void mma_tf32(float c[4],
                                         uint32_t a0, uint32_t a1, uint32_t a2, uint32_t a3,
                                         uint32_t b0, uint32_t b1) {
    asm volatile(
        "mma.sync.aligned.m16n8k8.row.col.f32.tf32.tf32.f32 "
        "{%0,%1,%2,%3}, {%4,%5,%6,%7}, {%8,%9}, {%0,%1,%2,%3};"
        : "+f"(c[0]), "+f"(c[1]), "+f"(c[2]), "+f"(c[3])
        : "r"(a0), "r"(a1), "r"(a2), "r"(a3), "r"(b0), "r"(b1));
}

// ---------------- GEMM (tensor core tf32): g_hh[row] = (A[row] @ W) * dinv[row] ----------------
// BM=128, BN=64, BK=32. 256 threads = 8 warps in 4(m) x 2(n); warp tile 32x32.
__global__ void __launch_bounds__(256)
k_gemm_tc(const float* __restrict__ Ain, const float* __restrict__ W,
          int N, int Fout, int useZ) {
    const int K = 128;
    const float* A = useZ ? (const float*)g_z : Ain;

    __shared__ uint32_t As[128][36];   // [m][k], pad 4 -> bank (4m+k)%32 conflict-free
    __shared__ uint32_t Ws[32][68];    // [k][n], pad 4 -> bank (4k+n)%32 conflict-free

    int tid  = threadIdx.x;
    int warp = tid >> 5, lane = tid & 31;
    int wm = warp >> 1, wn = warp & 1;
    int rb = blockIdx.x * 128, cb = blockIdx.y * 64;
    int grp = lane >> 2, tg = lane & 3;

    float c[2][4][4] = {};   // [m-frag][n-frag][c0..c3]

    for (int k0 = 0; k0 < K; k0 += 32) {
        // A tile: 128x32 floats = 1024 float4, 4 per thread
#pragma unroll
        for (int i = 0; i < 4; i++) {
            int idx = tid + i * 256;
            int row = idx >> 3;
            int cc  = (idx & 7) * 4;
            float4 v = make_float4(0.f, 0.f, 0.f, 0.f);
            if (rb + row < N) v = *(const float4*)(A + (size_t)(rb + row) * K + k0 + cc);
            As[row][cc + 0] = f2tf32(v.x);
            As[row][cc + 1] = f2tf32(v.y);
            As[row][cc + 2] = f2tf32(v.z);
            As[row][cc + 3] = f2tf32(v.w);
        }
        // W tile: 32x64 floats = 512 float4, 2 per thread
#pragma unroll
        for (int i = 0; i < 2; i++) {
            int idx = tid + i * 256;
            int kk = idx >> 4;
            int cc = (idx & 15) * 4;
            float4 v = *(const float4*)(W + (size_t)(k0 + kk) * Fout + cb + cc);
            Ws[kk][cc + 0] = f2tf32(v.x);
            Ws[kk][cc + 1] = f2tf32(v.y);
            Ws[kk][cc + 2] = f2tf32(v.z);
            Ws[kk][cc + 3] = f2tf32(v.w);
        }
        __syncthreads();

#pragma unroll
        for (int ks = 0; ks < 4; ks++) {
            int kb = ks * 8;
            uint32_t a[2][4], b[4][2];
#pragma unroll
            for (int mi = 0; mi < 2; mi++) {
                int r0 = wm * 32 + mi * 16 + grp;
                a[mi][0] = As[r0][kb + tg];
                a[mi][1] = As[r0 + 8][kb + tg];
                a[mi][2] = As[r0][kb + tg + 4];
                a[mi][3] = As[r0 + 8][kb + tg + 4];
            }
#pragma unroll
            for (int ni = 0; ni < 4; ni++) {
                int n0 = wn * 32 + ni * 8 + grp;
                b[ni][0] = Ws[kb + tg][n0];
                b[ni][1] = Ws[kb + tg + 4][n0];
            }
#pragma unroll
            for (int mi = 0; mi < 2; mi++)
#pragma unroll
                for (int ni = 0; ni < 4; ni++)
                    mma_tf32(c[mi][ni], a[mi][0], a[mi][1], a[mi][2], a[mi][3],
                             b[ni][0], b[ni][1]);
        }
        __syncthreads();
    }

    // epilogue: scale by dinv[row], store float2 per (thread, m-half, n-frag)
#pragma unroll
    for (int mi = 0; mi < 2; mi++) {
#pragma unroll
        for (int half = 0; half < 2; half++) {
            int row = rb + wm * 32 + mi * 16 + grp + half * 8;
            if (row < N) {
                float dv = g_dinv[row];
#pragma unroll
                for (int ni = 0; ni < 4; ni++) {
                    int col = cb + wn * 32 + ni * 8 + tg * 2;
                    float2 o = make_float2(c[mi][ni][half * 2 + 0] * dv,
                                           c[mi][ni][half * 2 + 1] * dv);
                    *(float2*)(g_hh + (size_t)row * Fout + col) = o;
                }
            }
        }
    }
}

// ---------------- Aggregation: out[v] = relu?( dinv[v]*(hh[v] + sum hh[src]) + b ) ----------------
template <int VEC>   // VEC=4 -> F=128, VEC=2 -> F=64
__global__ void k_agg(const float* __restrict__ bias, int N, int F, int relu, int toZ) {
    int warp = (blockIdx.x * blockDim.x + threadIdx.x) >> 5;
    int lane = threadIdx.x & 31;
    if (warp >= N) return;
    int v = warp;
    int fo = lane * VEC;
    const float* hh = g_hh;

    float acc[VEC];
    {
        const float* hv = hh + (size_t)v * F + fo;
        if (VEC == 4) {
            float4 t = *(const float4*)hv;
            acc[0] = t.x; acc[1] = t.y; acc[2] = t.z; acc[3] = t.w;
        } else {
            float2 t = *(const float2*)hv;
            acc[0] = t.x; acc[1] = t.y;
        }
    }
    int s0 = g_rowstart[v], s1 = g_rowstart[v + 1];
    for (int base = s0; base < s1; base += 32) {
        int cnt = min(32, s1 - base);
        int sl = (base + lane < s1) ? g_srcs[base + lane] : 0;
#pragma unroll 4
        for (int j = 0; j < cnt; j++) {
            int s = __shfl_sync(0xffffffff, sl, j);
            const float* hs = hh + (size_t)s * F + fo;
            if (VEC == 4) {
                float4 t = *(const float4*)hs;
                acc[0] += t.x; acc[1] += t.y; acc[2] += t.z; acc[3] += t.w;
            } else {
                float2 t = *(const float2*)hs;
                acc[0] += t.x; acc[1] += t.y;
            }
        }
    }
    float dv = g_dinv[v];
    float o[VEC];
#pragma unroll
    for (int i = 0; i < VEC; i++) {
        float val = acc[i] * dv + bias[fo + i];
        if (relu) val = fmaxf(val, 0.f);
        o[i] = val;
    }
    float* op = (toZ ? g_z : g_zout) + (size_t)v * F + fo;
    if (VEC == 4) *(float4*)op = make_float4(o[0], o[1], o[2], o[3]);
    else          *(float2*)op = make_float2(o[0], o[1]);
}

// ---------------- Decode: out[j] = dot(zout[a], zout[b]) over 64 dims ----------------
__global__ void k_decode(const int* __restrict__ eli, float* __restrict__ out, int L) {
    int warp = (blockIdx.x * blockDim.x + threadIdx.x) >> 5;
    int lane = threadIdx.x & 31;
    if (warp >= L) return;
    int a = eli[warp];
    int b = eli[(size_t)L + warp];
    float2 za = *(const float2*)(g_zout + (size_t)a * 64 + lane * 2);
    float2 zb = *(const float2*)(g_zout + (size_t)b * 64 + lane * 2);
    float p = za.x * zb.x + za.y * zb.y;
#pragma unroll
    for (int off = 16; off > 0; off >>= 1)
        p += __shfl_xor_sync(0xffffffff, p, off);
    if (lane == 0) out[warp] = p;
}

// ---------------- launch ----------------
extern "C" void kernel_launch(void* const* d_in, const int* in_sizes, int n_in,
                              void* d_out, int out_size) {
    const float* x   = (const float*)d_in[0];
    const int*   ei  = (const int*)d_in[1];    // int32 (JAX x64 disabled)
    const int*   eli = (const int*)d_in[2];
    const float* W1  = (const float*)d_in[3];
    const float* b1  = (const float*)d_in[4];
    const float* W2  = (const float*)d_in[5];
    const float* b2  = (const float*)d_in[6];
    const float* W3  = (const float*)d_in[7];
    const float* b3  = (const float*)d_in[8];
    float* out = (float*)d_out;

    // CSR build
    k_zero<<<(NNODES + 255) / 256, 256>>>(NNODES);
    k_count<<<(NEDGES + 255) / 256, 256>>>(ei, NEDGES);
    k_scan<<<1, 1024>>>(NNODES);
    k_fill<<<(NEDGES + 255) / 256, 256>>>(ei, NEDGES);

    dim3 gB(256);
    // layer 1: x @ W1 -> hh ; agg -> z (relu)
    {
        dim3 g((NNODES + 127) / 128, FHID / 64);
        k_gemm_tc<<<g, gB>>>(x, W1, NNODES, FHID, 0);
        k_agg<4><<<(NNODES * 32 + 255) / 256, 256>>>(b1, NNODES, 128, 1, 1);
    }
    // layer 2: z @ W2 -> hh ; agg -> z (relu)
    {
        dim3 g((NNODES + 127) / 128, FHID / 64);
        k_gemm_tc<<<g, gB>>>(nullptr, W2, NNODES, FHID, 1);
        k_agg<4><<<(NNODES * 32 + 255) / 256, 256>>>(b2, NNODES, 128, 1, 1);
    }
    // layer 3: z @ W3 -> hh(64-wide) ; agg -> zout (no relu)
    {
        dim3 g((NNODES + 127) / 128, FOUT / 64);
        k_gemm_tc<<<g, gB>>>(nullptr, W3, NNODES, FOUT, 1);
        k_agg<2><<<(NNODES * 32 + 255) / 256, 256>>>(b3, NNODES, 64, 0, 0);
    }
    // decode
    k_decode<<<(NLBL * 32 + 255) / 256, 256>>>(eli, out, NLBL);
}

// round 5
// speedup vs baseline: 2.0105x; 1.0652x over previous
#include <cuda_runtime.h>
#include <cstdint>

#define NNODES 50000
#define NEDGES 800000
#define NLBL   100000
#define FIN    128
#define FHID   128
#define FOUT   64

// ---------------- device scratch (static, no runtime allocation) ----------------
__device__ int   g_cnt[NNODES];
__device__ int   g_rowstart[NNODES + 1];   // after k_fill: g_rowstart[v] = END of v's range
__device__ float g_dinv[NNODES];
__device__ int   g_srcs[NEDGES];
__device__ __align__(16) float g_hh[(size_t)NNODES * 128];    // GEMM out, pre-scaled by dinv[row]
__device__ __align__(16) float g_z[(size_t)NNODES * 128];     // layer activation
__device__ __align__(16) float g_zout[(size_t)NNODES * 64];   // final embeddings

// ---------------- CSR build ----------------
__global__ void k_zero(int n) {
    int i = blockIdx.x * blockDim.x + threadIdx.x;
    if (i < n) g_cnt[i] = 0;
}

__global__ void k_count(const int* __restrict__ ei, int E) {
    int e = blockIdx.x * blockDim.x + threadIdx.x;   // handles edges 2e, 2e+1
    if (e * 2 >= E) return;
    int2 d = ((const int2*)(ei + E))[e];
    atomicAdd(&g_cnt[d.x], 1);
    atomicAdd(&g_cnt[d.y], 1);
}

// single-block exclusive scan over NNODES + dinv computation
__global__ void k_scan(int n) {
    const int T = 1024;
    const int CH = (NNODES + T - 1) / T;   // 49
    __shared__ int sums[T];
    int tid = threadIdx.x;
    int b = tid * CH;
    int e = min(b + CH, n);
    int s = 0;
    for (int i = b; i < e; i++) s += g_cnt[i];
    sums[tid] = s;
    __syncthreads();
    for (int off = 1; off < T; off <<= 1) {
        int t = 0;
        if (tid >= off) t = sums[tid - off];
        __syncthreads();
        sums[tid] += t;
        __syncthreads();
    }
    int run = sums[tid] - s;   // exclusive prefix
    for (int i = b; i < e; i++) {
        g_rowstart[i] = run;
        int c = g_cnt[i];
        run += c;
        g_dinv[i] = rsqrtf((float)c + 1.0f);
    }
    if (tid == T - 1) g_rowstart[n] = sums[T - 1];
}

// fill: atomically bump rowstart[d] itself; afterwards rowstart[v] == end(v)
__global__ void k_fill(const int* __restrict__ ei, int E) {
    int e = blockIdx.x * blockDim.x + threadIdx.x;   // handles edges 2e, 2e+1
    if (e * 2 >= E) return;
    int2 s = ((const int2*)ei)[e];
    int2 d = ((const int2*)(ei + E))[e];
    int p0 = atomicAdd(&g_rowstart[d.x], 1);
    g_srcs[p0] = s.x;
    int p1 = atomicAdd(&g_rowstart[d.y], 1);
    g_srcs[p1] = s.y;
}

// ---------------- helpers for tf32 tensor-core GEMM ----------------
__device__ __forceinline__ uint32_t f2tf32(float f) {
    uint32_t r;
    asm("cvt.rna.tf32.f32 %0, %1;" : "=r"(r) : "f"(f));
    return r;
}

__device__ __forceinline__ void mma_tf32(float c[4],
                                         uint32_t a0, uint32_t a1, uint32_t a2, uint32_t a3,
                                         uint32_t b0, uint32_t b1) {
    asm volatile(
        "mma.sync.aligned.m16n8k8.row.col.f32.tf32.tf32.f32 "
        "{%0,%1,%2,%3}, {%4,%5,%6,%7}, {%8,%9}, {%0,%1,%2,%3};"
        : "+f"(c[0]), "+f"(c[1]), "+f"(c[2]), "+f"(c[3])
        : "r"(a0), "r"(a1), "r"(a2), "r"(a3), "r"(b0), "r"(b1));
}

// ---------------- GEMM (tensor core tf32): g_hh[row] = (A[row] @ W) * dinv[row] ----------------
// BM=128, BN=64, BK=32. 256 threads = 8 warps in 4(m) x 2(n); warp tile 32x32.
__global__ void __launch_bounds__(256)
k_gemm_tc(const float* __restrict__ Ain, const float* __restrict__ W,
          int N, int Fout, int useZ) {
    const int K = 128;
    const float* A = useZ ? (const float*)g_z : Ain;

    __shared__ uint32_t As[128][36];   // [m][k], pad 4 -> conflict-free
    __shared__ uint32_t Ws[32][68];    // [k][n], pad 4 -> conflict-free

    int tid  = threadIdx.x;
    int warp = tid >> 5, lane = tid & 31;
    int wm = warp >> 1, wn = warp & 1;
    int rb = blockIdx.x * 128, cb = blockIdx.y * 64;
    int grp = lane >> 2, tg = lane & 3;

    float c[2][4][4] = {};   // [m-frag][n-frag][c0..c3]

    for (int k0 = 0; k0 < K; k0 += 32) {
#pragma unroll
        for (int i = 0; i < 4; i++) {
            int idx = tid + i * 256;
            int row = idx >> 3;
            int cc  = (idx & 7) * 4;
            float4 v = make_float4(0.f, 0.f, 0.f, 0.f);
            if (rb + row < N) v = *(const float4*)(A + (size_t)(rb + row) * K + k0 + cc);
            As[row][cc + 0] = f2tf32(v.x);
            As[row][cc + 1] = f2tf32(v.y);
            As[row][cc + 2] = f2tf32(v.z);
            As[row][cc + 3] = f2tf32(v.w);
        }
#pragma unroll
        for (int i = 0; i < 2; i++) {
            int idx = tid + i * 256;
            int kk = idx >> 4;
            int cc = (idx & 15) * 4;
            float4 v = *(const float4*)(W + (size_t)(k0 + kk) * Fout + cb + cc);
            Ws[kk][cc + 0] = f2tf32(v.x);
            Ws[kk][cc + 1] = f2tf32(v.y);
            Ws[kk][cc + 2] = f2tf32(v.z);
            Ws[kk][cc + 3] = f2tf32(v.w);
        }
        __syncthreads();

#pragma unroll
        for (int ks = 0; ks < 4; ks++) {
            int kb = ks * 8;
            uint32_t a[2][4], b[4][2];
#pragma unroll
            for (int mi = 0; mi < 2; mi++) {
                int r0 = wm * 32 + mi * 16 + grp;
                a[mi][0] = As[r0][kb + tg];
                a[mi][1] = As[r0 + 8][kb + tg];
                a[mi][2] = As[r0][kb + tg + 4];
                a[mi][3] = As[r0 + 8][kb + tg + 4];
            }
#pragma unroll
            for (int ni = 0; ni < 4; ni++) {
                int n0 = wn * 32 + ni * 8 + grp;
                b[ni][0] = Ws[kb + tg][n0];
                b[ni][1] = Ws[kb + tg + 4][n0];
            }
#pragma unroll
            for (int mi = 0; mi < 2; mi++)
#pragma unroll
                for (int ni = 0; ni < 4; ni++)
                    mma_tf32(c[mi][ni], a[mi][0], a[mi][1], a[mi][2], a[mi][3],
                             b[ni][0], b[ni][1]);
        }
        __syncthreads();
    }

#pragma unroll
    for (int mi = 0; mi < 2; mi++) {
#pragma unroll
        for (int half = 0; half < 2; half++) {
            int row = rb + wm * 32 + mi * 16 + grp + half * 8;
            if (row < N) {
                float dv = g_dinv[row];
#pragma unroll
                for (int ni = 0; ni < 4; ni++) {
                    int col = cb + wn * 32 + ni * 8 + tg * 2;
                    float2 o = make_float2(c[mi][ni][half * 2 + 0] * dv,
                                           c[mi][ni][half * 2 + 1] * dv);
                    *(float2*)(g_hh + (size_t)row * Fout + col) = o;
                }
            }
        }
    }
}

// ---------------- Aggregation: out[v] = relu?( dinv[v]*(hh[v] + sum hh[src]) + b ) ----------------
// Neighbor range of v is [rowstart[v-1], rowstart[v]) (rowstart holds ENDs after k_fill).
template <int VEC>   // VEC=4 -> F=128, VEC=2 -> F=64
__global__ void k_agg(const float* __restrict__ bias, int N, int F, int relu, int toZ) {
    int warp = (blockIdx.x * blockDim.x + threadIdx.x) >> 5;
    int lane = threadIdx.x & 31;
    if (warp >= N) return;
    int v = warp;
    int fo = lane * VEC;
    const float* __restrict__ hh = g_hh;

    float acc[VEC];
    {
        const float* hv = hh + (size_t)v * F + fo;
        if (VEC == 4) {
            float4 t = *(const float4*)hv;
            acc[0] = t.x; acc[1] = t.y; acc[2] = t.z; acc[3] = t.w;
        } else {
            float2 t = *(const float2*)hv;
            acc[0] = t.x; acc[1] = t.y;
        }
    }
    int e1 = __ldg(&g_rowstart[v]);
    int e0 = (v == 0) ? 0 : __ldg(&g_rowstart[v - 1]);

    int i = e0;
    // unroll-4: broadcast index loads (same address all lanes), 4 row loads in flight
    for (; i + 4 <= e1; i += 4) {
        int s0 = __ldg(&g_srcs[i + 0]);
        int s1 = __ldg(&g_srcs[i + 1]);
        int s2 = __ldg(&g_srcs[i + 2]);
        int s3 = __ldg(&g_srcs[i + 3]);
        if (VEC == 4) {
            float4 t0 = *(const float4*)(hh + (size_t)s0 * F + fo);
            float4 t1 = *(const float4*)(hh + (size_t)s1 * F + fo);
            float4 t2 = *(const float4*)(hh + (size_t)s2 * F + fo);
            float4 t3 = *(const float4*)(hh + (size_t)s3 * F + fo);
            acc[0] += t0.x + t1.x + t2.x + t3.x;
            acc[1] += t0.y + t1.y + t2.y + t3.y;
            acc[2] += t0.z + t1.z + t2.z + t3.z;
            acc[3] += t0.w + t1.w + t2.w + t3.w;
        } else {
            float2 t0 = *(const float2*)(hh + (size_t)s0 * F + fo);
            float2 t1 = *(const float2*)(hh + (size_t)s1 * F + fo);
            float2 t2 = *(const float2*)(hh + (size_t)s2 * F + fo);
            float2 t3 = *(const float2*)(hh + (size_t)s3 * F + fo);
            acc[0] += t0.x + t1.x + t2.x + t3.x;
            acc[1] += t0.y + t1.y + t2.y + t3.y;
        }
    }
    for (; i < e1; i++) {
        int s = __ldg(&g_srcs[i]);
        const float* hs = hh + (size_t)s * F + fo;
        if (VEC == 4) {
            float4 t = *(const float4*)hs;
            acc[0] += t.x; acc[1] += t.y; acc[2] += t.z; acc[3] += t.w;
        } else {
            float2 t = *(const float2*)hs;
            acc[0] += t.x; acc[1] += t.y;
        }
    }

    float dv = g_dinv[v];
    float o[VEC];
#pragma unroll
    for (int k = 0; k < VEC; k++) {
        float val = acc[k] * dv + bias[fo + k];
        if (relu) val = fmaxf(val, 0.f);
        o[k] = val;
    }
    float* op = (toZ ? g_z : g_zout) + (size_t)v * F + fo;
    if (VEC == 4) *(float4*)op = make_float4(o[0], o[1], o[2], o[3]);
    else          *(float2*)op = make_float2(o[0], o[1]);
}

// ---------------- Decode: out[j] = dot(zout[a], zout[b]) over 64 dims ----------------
__global__ void k_decode(const int* __restrict__ eli, float* __restrict__ out, int L) {
    int warp = (blockIdx.x * blockDim.x + threadIdx.x) >> 5;
    int lane = threadIdx.x & 31;
    if (warp >= L) return;
    int a = eli[warp];
    int b = eli[(size_t)L + warp];
    float2 za = *(const float2*)(g_zout + (size_t)a * 64 + lane * 2);
    float2 zb = *(const float2*)(g_zout + (size_t)b * 64 + lane * 2);
    float p = za.x * zb.x + za.y * zb.y;
#pragma unroll
    for (int off = 16; off > 0; off >>= 1)
        p += __shfl_xor_sync(0xffffffff, p, off);
    if (lane == 0) out[warp] = p;
}

// ---------------- launch ----------------
extern "C" void kernel_launch(void* const* d_in, const int* in_sizes, int n_in,
                              void* d_out, int out_size) {
    const float* x   = (const float*)d_in[0];
    const int*   ei  = (const int*)d_in[1];    // int32 (JAX x64 disabled)
    const int*   eli = (const int*)d_in[2];
    const float* W1  = (const float*)d_in[3];
    const float* b1  = (const float*)d_in[4];
    const float* W2  = (const float*)d_in[5];
    const float* b2  = (const float*)d_in[6];
    const float* W3  = (const float*)d_in[7];
    const float* b3  = (const float*)d_in[8];
    float* out = (float*)d_out;

    // CSR build
    k_zero<<<(NNODES + 255) / 256, 256>>>(NNODES);
    k_count<<<(NEDGES / 2 + 255) / 256, 256>>>(ei, NEDGES);
    k_scan<<<1, 1024>>>(NNODES);
    k_fill<<<(NEDGES / 2 + 255) / 256, 256>>>(ei, NEDGES);

    dim3 gB(256);
    // layer 1: x @ W1 -> hh ; agg -> z (relu)
    {
        dim3 g((NNODES + 127) / 128, FHID / 64);
        k_gemm_tc<<<g, gB>>>(x, W1, NNODES, FHID, 0);
        k_agg<4><<<(NNODES * 32 + 255) / 256, 256>>>(b1, NNODES, 128, 1, 1);
    }
    // layer 2: z @ W2 -> hh ; agg -> z (relu)
    {
        dim3 g((NNODES + 127) / 128, FHID / 64);
        k_gemm_tc<<<g, gB>>>(nullptr, W2, NNODES, FHID, 1);
        k_agg<4><<<(NNODES * 32 + 255) / 256, 256>>>(b2, NNODES, 128, 1, 1);
    }
    // layer 3: z @ W3 -> hh(64-wide) ; agg -> zout (no relu)
    {
        dim3 g((NNODES + 127) / 128, FOUT / 64);
        k_gemm_tc<<<g, gB>>>(nullptr, W3, NNODES, FOUT, 1);
        k_agg<2><<<(NNODES * 32 + 255) / 256, 256>>>(b3, NNODES, 64, 0, 0);
    }
    // decode
    k_decode<<<(NLBL * 32 + 255) / 256, 256>>>(eli, out, NLBL);
}